// round 12
// baseline (speedup 1.0000x reference)
#include <cuda_runtime.h>
#include <cuda_fp16.h>
#include <math.h>
#include <stdint.h>

#define NPOS 2304
#define FEATSZ (2*2*4*128*NPOS)

// Scratch
__device__ float  g_feat2[FEATSZ];
__device__ float  g_m[FEATSZ];
__device__ float  g_z[FEATSZ];
__device__ float  g_r[FEATSZ];
__device__ __half g_wth[2*4*9*128*512];  // conv weights [mn][tap][co][ci], fp16
__device__ __half g_gwh[2*3*128*256];    // gru weights  [mod][gate][o][k], fp16
__device__ __half g_inh[2*2*64*NPOS*8];  // conv input   [mb][cg][pos][8ci], fp16
__device__ float  g_gate[2*2*12*NPOS];   // edge gates   [modb][i*3+k][pos]

__device__ __forceinline__ float sigm(float x) { return 1.f / (1.f + expf(-x)); }

__device__ __forceinline__ void mma_f16(float* c, const uint32_t* a, const uint32_t* b) {
    asm volatile(
        "mma.sync.aligned.m16n8k16.row.col.f32.f16.f16.f32 "
        "{%0,%1,%2,%3}, {%4,%5,%6,%7}, {%8,%9}, {%0,%1,%2,%3};"
        : "+f"(c[0]), "+f"(c[1]), "+f"(c[2]), "+f"(c[3])
        : "r"(a[0]), "r"(a[1]), "r"(a[2]), "r"(a[3]), "r"(b[0]), "r"(b[1]));
}

#define CPA16(dst, src) \
    asm volatile("cp.async.cg.shared.global [%0], [%1], 16;" :: "r"(dst), "l"(src))
#define CPA16Z(dst, src, nbytes) \
    asm volatile("cp.async.cg.shared.global [%0], [%1], 16, %2;" \
                 :: "r"(dst), "l"(src), "r"(nbytes))
#define CPA_COMMIT() asm volatile("cp.async.commit_group;" ::: "memory")
#define CPA_WAIT1()  asm volatile("cp.async.wait_group 1;" ::: "memory")
#define CPA_WAIT0()  asm volatile("cp.async.wait_group 0;" ::: "memory")

// ---------------------------------------------------------------------------
// Prep kernels
// ---------------------------------------------------------------------------
__global__ void wt_prep_kernel(const float* __restrict__ wR, const float* __restrict__ wD)
{
    int e = blockIdx.x * 256 + threadIdx.x;
    if (e >= 2*4*9*128*512) return;
    int ci = e & 511;
    int r = e >> 9;
    int co = r & 127; r >>= 7;
    int tap = r % 9; r /= 9;
    int node = r & 3;
    int mod = r >> 2;
    const float* w = mod ? wD : wR;
    g_wth[e] = __float2half_rn(w[((size_t)(node*128 + co)*512 + ci)*9 + tap]);
}

__global__ void gwh_prep_kernel(const float* __restrict__ gwR, const float* __restrict__ gwD)
{
    int e = blockIdx.x * 256 + threadIdx.x;
    if (e >= 2*3*128*256) return;
    int mod = e / (3*128*256);
    int x   = e % (3*128*256);
    const float* w = mod ? gwD : gwR;
    g_gwh[e] = __float2half_rn(w[x]);
}

// 8-channel group interleave: g_inh[((mb*64 + cg)*NPOS + pos)*8 + j], ci = cg*8+j
__global__ void in_prep_kernel(const float* __restrict__ inR, const float* __restrict__ inD)
{
    int e = blockIdx.x * 256 + threadIdx.x;
    if (e >= 4 * 64 * NPOS) return;
    int pos = e % NPOS;
    int r = e / NPOS;
    int cg = r & 63;
    int mb = r >> 6;                 // mod*2 + b
    const float* src = ((mb >> 1) ? inD : inR)
                     + ((size_t)(mb & 1) * 512 + cg * 8) * NPOS + pos;
    __half v[8];
#pragma unroll
    for (int j = 0; j < 8; j++) v[j] = __float2half_rn(src[(size_t)j * NPOS]);
    *(uint4*)&g_inh[((size_t)(mb * 64 + cg) * NPOS + pos) * 8] = *(uint4*)v;
}

// ---------------------------------------------------------------------------
// Conv via mma.sync fp16 m16n8k16 implicit GEMM; 16B cp.async staging, K64.
// grid: (48 = b*24 + rowpair, 8 = mod*4+node), 256 threads (8 warps: 4m x 2n)
// Stages: 72 (tap 0..8 x 8 chunks of 64 ci). Dynamic smem 64.5 KB.
// ---------------------------------------------------------------------------
#define CPA_H 72
#define CA_BUF (128*CPA_H)
#define CB_BUF (96*CPA_H)
#define CONV_SMEM ((2*CA_BUF + 2*CB_BUF)*2)

__global__ __launch_bounds__(256)
void conv_mma_kernel(const float* __restrict__ sR, const float* __restrict__ bR,
                     const float* __restrict__ sD, const float* __restrict__ bD,
                     float* __restrict__ out)
{
    extern __shared__ __half csm[];
    __half* smA = csm;                    // [2][CA_BUF]
    __half* smB = csm + 2 * CA_BUF;       // [2][CB_BUF]

    const int tid = threadIdx.x;
    const int lane = tid & 31;
    const int wid = tid >> 5;
    const int wm = wid & 3;
    const int wn = wid >> 2;

    const int mn   = blockIdx.y;
    const int mod  = mn >> 2, node = mn & 3;
    const int dil  = 1 << node;
    const int b    = blockIdx.x / 24;
    const int y0   = (blockIdx.x % 24) * 2;

    const __half* __restrict__ inh = g_inh + (size_t)(mod * 2 + b) * 64 * NPOS * 8;
    const __half* __restrict__ Wt  = g_wth + (size_t)mn * 9 * 128 * 512;

    const int arow = tid >> 1;             // 0..127
    const int ahb  = (tid & 1) * 32;       // half of the 64-ci row

    const uint32_t smA_u32 = (uint32_t)__cvta_generic_to_shared(smA);
    const uint32_t smB_u32 = (uint32_t)__cvta_generic_to_shared(smB);

    // B task decomposition: 96 pos x 8 cg = 768 tasks, 3 per thread
    int bposl[3], bcg[3];
#pragma unroll
    for (int i = 0; i < 3; i++) {
        int t = tid + 256 * i;
        bcg[i]  = t / 96;
        bposl[i] = t - bcg[i] * 96;
    }

    float acc[2][6][4];
#pragma unroll
    for (int i = 0; i < 2; i++)
#pragma unroll
        for (int j = 0; j < 6; j++)
#pragma unroll
            for (int k = 0; k < 4; k++) acc[i][j][k] = 0.f;

#define STAGE(S, BUF) do {                                                    \
    int tap_ = (S) >> 3;                                                      \
    int cc_  = ((S) & 7) * 64;                                                \
    int dy_  = (tap_ / 3 - 1) * dil;                                          \
    int dx_  = (tap_ % 3 - 1) * dil;                                          \
    { const __half* wsrc = Wt + ((size_t)(tap_ * 128) + arow) * 512 + cc_ + ahb; \
      uint32_t ad = smA_u32 + (uint32_t)(BUF) * (CA_BUF * 2)                  \
                  + (uint32_t)(arow * CPA_H + ahb) * 2;                       \
      CPA16(ad, wsrc); CPA16(ad + 16, wsrc + 8);                              \
      CPA16(ad + 32, wsrc + 16); CPA16(ad + 48, wsrc + 24); }                 \
    _Pragma("unroll")                                                         \
    for (int i = 0; i < 3; i++) {                                             \
        int posl = bposl[i];                                                  \
        int cgl  = bcg[i];                                                    \
        int ry = posl / 48;                                                   \
        int x  = posl - ry * 48;                                              \
        int xs = x + dx_, ys = y0 + ry + dy_;                                 \
        bool ok = ((unsigned)xs < 48u) && ((unsigned)ys < 48u);               \
        int goff = ok ? (ys * 48 + xs) : 0;                                   \
        uint32_t nb = ok ? 16u : 0u;                                          \
        const __half* src = inh + ((size_t)((cc_ >> 3) + cgl) * NPOS + goff) * 8; \
        uint32_t bd = smB_u32 + (uint32_t)(BUF) * (CB_BUF * 2)                \
                    + (uint32_t)(posl * CPA_H + cgl * 8) * 2;                 \
        CPA16Z(bd, src, nb);                                                  \
    }                                                                         \
    CPA_COMMIT();                                                             \
} while (0)

    STAGE(0, 0);

    const int m0 = wm * 32;
    const int n0 = wn * 48;
    const int arow0 = lane >> 2;
    const int acol0 = lane & 3;
    const int brow0 = lane & 3;
    const int bcol0 = lane >> 2;

    for (int s = 0; s < 72; s++) {
        int buf = s & 1;
        if (s + 1 < 72) {
            STAGE(s + 1, buf ^ 1);
            CPA_WAIT1();
        } else {
            CPA_WAIT0();
        }
        __syncthreads();

        const __half* A_ = smA + buf * CA_BUF;
        const __half* B_ = smB + buf * CB_BUF;
#pragma unroll
        for (int k0 = 0; k0 < 64; k0 += 16) {
            uint32_t af[2][4];
#pragma unroll
            for (int mt = 0; mt < 2; mt++) {
                int r = m0 + mt * 16 + arow0;
                af[mt][0] = *(const uint32_t*)&A_[r * CPA_H + k0 + 2 * acol0];
                af[mt][1] = *(const uint32_t*)&A_[(r + 8) * CPA_H + k0 + 2 * acol0];
                af[mt][2] = *(const uint32_t*)&A_[r * CPA_H + k0 + 2 * acol0 + 8];
                af[mt][3] = *(const uint32_t*)&A_[(r + 8) * CPA_H + k0 + 2 * acol0 + 8];
            }
#pragma unroll
            for (int nt = 0; nt < 6; nt++) {
                int ncol = n0 + nt * 8 + bcol0;
                uint32_t bf[2];
                bf[0] = *(const uint32_t*)&B_[ncol * CPA_H + k0 + 2 * brow0];
                bf[1] = *(const uint32_t*)&B_[ncol * CPA_H + k0 + 2 * brow0 + 8];
                mma_f16(acc[0][nt], af[0], bf);
                mma_f16(acc[1][nt], af[1], bf);
            }
        }
        __syncthreads();
    }

    const float* sc = (mod ? sD : sR) + node * 128;
    const float* bi = (mod ? bD : bR) + node * 128;
    float* outp = out + ((size_t)((mod * 2 + b) * 4 + node) * 128) * NPOS + y0 * 48;

#pragma unroll
    for (int mt = 0; mt < 2; mt++) {
#pragma unroll
        for (int half = 0; half < 2; half++) {
            int co = m0 + mt * 16 + half * 8 + (lane >> 2);
            float s = __ldg(sc + co), bb = __ldg(bi + co);
            float* orow = outp + (size_t)co * NPOS;
#pragma unroll
            for (int nt = 0; nt < 6; nt++) {
                int pos = n0 + nt * 8 + (lane & 3) * 2;
                float v0 = fmaxf(fmaf(acc[mt][nt][half * 2 + 0], s, bb), 0.f);
                float v1 = fmaxf(fmaf(acc[mt][nt][half * 2 + 1], s, bb), 0.f);
                *(float2*)(orow + pos) = make_float2(v0, v1);
            }
        }
    }
#undef STAGE
}

// ---------------------------------------------------------------------------
// PA: register-resident cross-modal gating (proven)
// ---------------------------------------------------------------------------
__global__ __launch_bounds__(256)
void pa_kernel(float* __restrict__ feat, const float* __restrict__ paw)
{
    const int pl = threadIdx.x & 63;
    const int cs = threadIdx.x >> 6;
    const int bn  = blockIdx.x / 36;
    const int pos = (blockIdx.x % 36) * 64 + pl;
    float* pr = feat + (size_t)bn * 128 * NPOS + pos;
    float* pd = feat + (size_t)(8 + bn) * 128 * NPOS + pos;

    float r[32], d[32];
#pragma unroll 8
    for (int j = 0; j < 32; j++) {
        int c = cs * 32 + j;
        r[j] = pr[(size_t)c * NPOS];
        d[j] = pd[(size_t)c * NPOS];
    }

    __shared__ float red[2][4][2][64];

#pragma unroll
    for (int it = 0; it < 2; it++) {
        float s0 = 0.f, s1 = 0.f;
#pragma unroll 8
        for (int j = 0; j < 32; j++) {
            int c = cs * 32 + j;
            float df = r[j] - d[j];
            s0 = fmaf(df,  __ldg(paw + c),       s0);
            s1 = fmaf(-df, __ldg(paw + 128 + c), s1);
        }
        red[it][cs][0][pl] = s0;
        red[it][cs][1][pl] = s1;
        __syncthreads();
        float S0 = red[it][0][0][pl] + red[it][1][0][pl] + red[it][2][0][pl] + red[it][3][0][pl];
        float S1 = red[it][0][1][pl] + red[it][1][1][pl] + red[it][2][1][pl] + red[it][3][1][pl];
        float g0 = sigm(S0), g1 = sigm(S1);
#pragma unroll 8
        for (int j = 0; j < 32; j++) {
            float t = r[j];
            r[j] = fmaf(d[j], g1, t);
            d[j] = fmaf(t, g0, d[j]);
        }
    }

#pragma unroll 8
    for (int j = 0; j < 32; j++) {
        int c = cs * 32 + j;
        pr[(size_t)c * NPOS] = r[j];
        pd[(size_t)c * NPOS] = d[j];
    }
}

// ---------------------------------------------------------------------------
// g1a: edge gates (proven)
// ---------------------------------------------------------------------------
__global__ __launch_bounds__(256)
void g1a_kernel(const float* __restrict__ dout, int it,
                const float* __restrict__ wgtR, const float* __restrict__ wgtD)
{
    const float* feat = it ? g_feat2 : dout;
    const int pl = threadIdx.x & 63;
    const int cs = threadIdx.x >> 6;
    const int pos = blockIdx.x * 64 + pl;
    const int b = blockIdx.y, mod = blockIdx.z;
    const float* wgt = mod ? wgtD : wgtR;
    const int modb = mod * 2 + b;
    size_t base = (size_t)(modb * 4) * 128 * NPOS;
    const float* f = feat + base + pos;

    float s[3][4];
#pragma unroll
    for (int k = 0; k < 3; k++)
#pragma unroll
        for (int p = 0; p < 4; p++) s[k][p] = 0.f;

#pragma unroll 4
    for (int j = 0; j < 32; j++) {
        int c = cs * 32 + j;
        float w0 = __ldg(wgt + c), w1 = __ldg(wgt + 128 + c), w2 = __ldg(wgt + 256 + c);
#pragma unroll
        for (int p = 0; p < 4; p++) {
            float fv = f[(size_t)(p * 128 + c) * NPOS];
            s[0][p] = fmaf(w0, fv, s[0][p]);
            s[1][p] = fmaf(w1, fv, s[1][p]);
            s[2][p] = fmaf(w2, fv, s[2][p]);
        }
    }

    __shared__ float red[4][12][64];
#pragma unroll
    for (int k = 0; k < 3; k++)
#pragma unroll
        for (int p = 0; p < 4; p++)
            red[cs][k * 4 + p][pl] = s[k][p];
    __syncthreads();

    if (threadIdx.x < 64) {
        float ss[12];
#pragma unroll
        for (int j = 0; j < 12; j++)
            ss[j] = red[0][j][pl] + red[1][j][pl] + red[2][j][pl] + red[3][j][pl];

        const int OI[4][3] = {{1,2,3},{0,2,3},{0,1,3},{0,1,2}};
#pragma unroll
        for (int i = 0; i < 4; i++)
#pragma unroll
            for (int k = 0; k < 3; k++) {
                float sg = sigm(ss[k * 4 + i] - ss[k * 4 + OI[i][k]]);
                g_gate[(size_t)(modb * 12 + i * 3 + k) * NPOS + pos] = sg;
            }
    }
}

// ---------------------------------------------------------------------------
// g1b: messages (proven)
// ---------------------------------------------------------------------------
__global__ __launch_bounds__(256)
void g1b_kernel(const float* __restrict__ dout, int it)
{
    const float* feat = it ? g_feat2 : dout;
    const int c   = blockIdx.x / 9;
    const int pos = (blockIdx.x % 9) * 256 + threadIdx.x;
    const int b = blockIdx.y, mod = blockIdx.z;
    const int modb = mod * 2 + b;
    size_t base = (size_t)(modb * 4) * 128 * NPOS;
    const float* f = feat + base + (size_t)c * NPOS + pos;

    float fv[4];
#pragma unroll
    for (int p = 0; p < 4; p++) fv[p] = f[(size_t)(p * 128) * NPOS];

    float sg[12];
#pragma unroll
    for (int g = 0; g < 12; g++)
        sg[g] = g_gate[(size_t)(modb * 12 + g) * NPOS + pos];

    const int OI[4][3] = {{1,2,3},{0,2,3},{0,1,3},{0,1,2}};
    const int c3 = c % 3;
    float* mo = g_m + base + (size_t)c * NPOS + pos;
#pragma unroll
    for (int i = 0; i < 4; i++) {
        float msum = 0.f;
#pragma unroll
        for (int k = 0; k < 3; k++) {
            int gi = 2 * k + c3;
            if (gi >= 3) gi -= 3;
            if (gi >= 3) gi -= 3;
            msum = fmaf(fv[OI[i][k]], sg[i * 3 + gi], msum);
        }
        mo[(size_t)(i * 128) * NPOS] = msum;
    }
}

// ---------------------------------------------------------------------------
// g2 via mma.sync fp16 (proven)
// ---------------------------------------------------------------------------
#define PA_H 40
#define PB_H 40
#define A_BUF_H (128*PA_H)
#define B_BUF_H (96*PB_H)

__global__ __launch_bounds__(256)
void g2_mma_kernel(const float* __restrict__ dout, int it,
                   const float* __restrict__ gbR, const float* __restrict__ gbD)
{
    __shared__ __half smA[2][A_BUF_H];
    __shared__ __half smB[2][B_BUF_H];

    const float* feat = it ? g_feat2 : dout;
    const int tid = threadIdx.x;
    const int lane = tid & 31;
    const int wid = tid >> 5;
    const int wm = wid & 3;
    const int wn = wid >> 2;

    const int zid = blockIdx.z;
    const int mod = zid >> 3, bn = zid & 7;
    const int oblk = blockIdx.y;
    const int col0 = blockIdx.x * 96;

    const __half* Agw = g_gwh + (size_t)mod * 3 * 128 * 256 + (size_t)oblk * 128 * 256;
    const float* bias = (mod ? gbD : gbR) + oblk * 128;
    size_t base = (size_t)(mod * 8 + bn) * 128 * NPOS;
    const float* F = feat + base;
    const float* M = g_m + base;

    const int arow = tid >> 1;
    const int ahb  = (tid & 1) * 16;

    float acc[2][6][4];
#pragma unroll
    for (int i = 0; i < 2; i++)
#pragma unroll
        for (int j = 0; j < 6; j++)
#pragma unroll
            for (int k = 0; k < 4; k++) acc[i][j][k] = 0.f;

#define GSTAGE(S, BUF) do {                                                   \
    int cc_ = (S) * 32;                                                       \
    { const __half* wsrc = Agw + (size_t)arow * 256 + cc_ + ahb;              \
      uint4 v0 = *(const uint4*)(wsrc);                                       \
      uint4 v1 = *(const uint4*)(wsrc + 8);                                   \
      __half* ad = &smA[BUF][arow * PA_H + ahb];                              \
      *(uint4*)(ad) = v0; *(uint4*)(ad + 8) = v1; }                           \
    _Pragma("unroll")                                                         \
    for (int pb = 0; pb < 3; pb++) {                                          \
        int col = lane + 32 * pb;                                             \
        _Pragma("unroll")                                                     \
        for (int pp = 0; pp < 2; pp++) {                                      \
            int x = cc_ + 2 * (wid + 8 * pp);                                 \
            float v0, v1;                                                     \
            if (x < 128) {                                                    \
                v0 = M[(size_t)x * NPOS + col0 + col];                        \
                v1 = M[(size_t)(x + 1) * NPOS + col0 + col];                  \
            } else {                                                          \
                v0 = F[(size_t)(x - 128) * NPOS + col0 + col];                \
                v1 = F[(size_t)(x - 127) * NPOS + col0 + col];                \
            }                                                                 \
            *(half2*)&smB[BUF][col * PB_H + (x - cc_)] = __floats2half2_rn(v0, v1); \
        }                                                                     \
    }                                                                         \
} while (0)

    GSTAGE(0, 0);
    __syncthreads();

    const int m0 = wm * 32;
    const int n0 = wn * 48;
    const int arow0 = lane >> 2;
    const int acol0 = lane & 3;
    const int brow0 = lane & 3;
    const int bcol0 = lane >> 2;

    for (int s = 0; s < 8; s++) {
        int buf = s & 1;
        if (s + 1 < 8) GSTAGE(s + 1, buf ^ 1);

        const __half* A_ = smA[buf];
        const __half* B_ = smB[buf];
#pragma unroll
        for (int k0 = 0; k0 < 32; k0 += 16) {
            uint32_t af[2][4];
#pragma unroll
            for (int mt = 0; mt < 2; mt++) {
                int r = m0 + mt * 16 + arow0;
                af[mt][0] = *(const uint32_t*)&A_[r * PA_H + k0 + 2 * acol0];
                af[mt][1] = *(const uint32_t*)&A_[(r + 8) * PA_H + k0 + 2 * acol0];
                af[mt][2] = *(const uint32_t*)&A_[r * PA_H + k0 + 2 * acol0 + 8];
                af[mt][3] = *(const uint32_t*)&A_[(r + 8) * PA_H + k0 + 2 * acol0 + 8];
            }
#pragma unroll
            for (int nt = 0; nt < 6; nt++) {
                int ncol = n0 + nt * 8 + bcol0;
                uint32_t bf[2];
                bf[0] = *(const uint32_t*)&B_[ncol * PB_H + k0 + 2 * brow0];
                bf[1] = *(const uint32_t*)&B_[ncol * PB_H + k0 + 2 * brow0 + 8];
                mma_f16(acc[0][nt], af[0], bf);
                mma_f16(acc[1][nt], af[1], bf);
            }
        }
        __syncthreads();
    }

    float* ob = (oblk == 0) ? (g_z + base) : (g_r + base);
#pragma unroll
    for (int mt = 0; mt < 2; mt++) {
#pragma unroll
        for (int half = 0; half < 2; half++) {
            int o = m0 + mt * 16 + half * 8 + (lane >> 2);
            float bv = __ldg(bias + o);
            float* orow = ob + (size_t)o * NPOS + col0;
#pragma unroll
            for (int nt = 0; nt < 6; nt++) {
                int col = n0 + nt * 8 + (lane & 3) * 2;
                orow[col]     = sigm(acc[mt][nt][half * 2 + 0] + bv);
                orow[col + 1] = sigm(acc[mt][nt][half * 2 + 1] + bv);
            }
        }
    }
#undef GSTAGE
}

// ---------------------------------------------------------------------------
// g3 via mma.sync fp16 (proven)
// ---------------------------------------------------------------------------
__global__ __launch_bounds__(256)
void g3_mma_kernel(float* __restrict__ dout, int it,
                   const float* __restrict__ gbR, const float* __restrict__ gbD,
                   const float* __restrict__ gamR, const float* __restrict__ gamD)
{
    __shared__ __half smA[2][A_BUF_H];
    __shared__ __half smB[2][B_BUF_H];

    const float* feat = it ? g_feat2 : dout;
    float* dst        = it ? dout : g_feat2;
    const int tid = threadIdx.x;
    const int lane = tid & 31;
    const int wid = tid >> 5;
    const int wm = wid & 3;
    const int wn = wid >> 2;

    const int zid = blockIdx.z;
    const int mod = zid >> 3, bn = zid & 7;
    const int col0 = blockIdx.x * 96;

    const __half* Agw = g_gwh + (size_t)mod * 3 * 128 * 256 + (size_t)2 * 128 * 256;
    const float* bias = (mod ? gbD : gbR) + 2 * 128;
    float gam = mod ? __ldg(gamD) : __ldg(gamR);
    size_t base = (size_t)(mod * 8 + bn) * 128 * NPOS;
    const float* F = feat + base;
    const float* M = g_m + base;
    const float* R = g_r + base;

    const int arow = tid >> 1;
    const int ahb  = (tid & 1) * 16;

    float acc[2][6][4];
#pragma unroll
    for (int i = 0; i < 2; i++)
#pragma unroll
        for (int j = 0; j < 6; j++)
#pragma unroll
            for (int k = 0; k < 4; k++) acc[i][j][k] = 0.f;

#define G3STAGE(S, BUF) do {                                                  \
    int cc_ = (S) * 32;                                                       \
    { const __half* wsrc = Agw + (size_t)arow * 256 + cc_ + ahb;              \
      uint4 v0 = *(const uint4*)(wsrc);                                       \
      uint4 v1 = *(const uint4*)(wsrc + 8);                                   \
      __half* ad = &smA[BUF][arow * PA_H + ahb];                              \
      *(uint4*)(ad) = v0; *(uint4*)(ad + 8) = v1; }                           \
    _Pragma("unroll")                                                         \
    for (int pb = 0; pb < 3; pb++) {                                          \
        int col = lane + 32 * pb;                                             \
        _Pragma("unroll")                                                     \
        for (int pp = 0; pp < 2; pp++) {                                      \
            int x = cc_ + 2 * (wid + 8 * pp);                                 \
            float v0, v1;                                                     \
            if (x < 128) {                                                    \
                v0 = M[(size_t)x * NPOS + col0 + col];                        \
                v1 = M[(size_t)(x + 1) * NPOS + col0 + col];                  \
            } else {                                                          \
                size_t i0 = (size_t)(x - 128) * NPOS + col0 + col;            \
                size_t i1 = (size_t)(x - 127) * NPOS + col0 + col;            \
                v0 = F[i0] * R[i0];                                           \
                v1 = F[i1] * R[i1];                                           \
            }                                                                 \
            *(half2*)&smB[BUF][col * PB_H + (x - cc_)] = __floats2half2_rn(v0, v1); \
        }                                                                     \
    }                                                                         \
} while (0)

    G3STAGE(0, 0);
    __syncthreads();

    const int m0 = wm * 32;
    const int n0 = wn * 48;
    const int arow0 = lane >> 2;
    const int acol0 = lane & 3;
    const int brow0 = lane & 3;
    const int bcol0 = lane >> 2;

    for (int s = 0; s < 8; s++) {
        int buf = s & 1;
        if (s + 1 < 8) G3STAGE(s + 1, buf ^ 1);

        const __half* A_ = smA[buf];
        const __half* B_ = smB[buf];
#pragma unroll
        for (int k0 = 0; k0 < 32; k0 += 16) {
            uint32_t af[2][4];
#pragma unroll
            for (int mt = 0; mt < 2; mt++) {
                int r = m0 + mt * 16 + arow0;
                af[mt][0] = *(const uint32_t*)&A_[r * PA_H + k0 + 2 * acol0];
                af[mt][1] = *(const uint32_t*)&A_[(r + 8) * PA_H + k0 + 2 * acol0];
                af[mt][2] = *(const uint32_t*)&A_[r * PA_H + k0 + 2 * acol0 + 8];
                af[mt][3] = *(const uint32_t*)&A_[(r + 8) * PA_H + k0 + 2 * acol0 + 8];
            }
#pragma unroll
            for (int nt = 0; nt < 6; nt++) {
                int ncol = n0 + nt * 8 + bcol0;
                uint32_t bf[2];
                bf[0] = *(const uint32_t*)&B_[ncol * PB_H + k0 + 2 * brow0];
                bf[1] = *(const uint32_t*)&B_[ncol * PB_H + k0 + 2 * brow0 + 8];
                mma_f16(acc[0][nt], af[0], bf);
                mma_f16(acc[1][nt], af[1], bf);
            }
        }
        __syncthreads();
    }

#pragma unroll
    for (int mt = 0; mt < 2; mt++) {
#pragma unroll
        for (int half = 0; half < 2; half++) {
            int o = m0 + mt * 16 + half * 8 + (lane >> 2);
            float bv = __ldg(bias + o);
#pragma unroll
            for (int nt = 0; nt < 6; nt++) {
                int col = col0 + n0 + nt * 8 + (lane & 3) * 2;
#pragma unroll
                for (int u = 0; u < 2; u++) {
                    size_t idx = base + (size_t)o * NPOS + col + u;
                    float cand = tanhf(acc[mt][nt][half * 2 + u] + bv);
                    float z = g_z[idx];
                    float f = feat[idx];
                    dst[idx] = fmaf(gam, fmaf(f, 1.f - z, cand * z), f);
                }
            }
        }
    }
#undef G3STAGE
}

// ---------------------------------------------------------------------------
extern "C" void kernel_launch(void* const* d_in, const int* in_sizes, int n_in,
                              void* d_out, int out_size)
{
    const float* feat_rgb = (const float*)d_in[0];
    const float* feat_dep = (const float*)d_in[1];
    const float* ppm_w_r  = (const float*)d_in[2];
    const float* ppm_s_r  = (const float*)d_in[3];
    const float* ppm_b_r  = (const float*)d_in[4];
    const float* ppm_w_d  = (const float*)d_in[5];
    const float* ppm_s_d  = (const float*)d_in[6];
    const float* ppm_b_d  = (const float*)d_in[7];
    const float* pa_w     = (const float*)d_in[8];
    const float* wgt_r    = (const float*)d_in[9];
    const float* gruw_r   = (const float*)d_in[10];
    const float* grub_r   = (const float*)d_in[11];
    const float* gam_r    = (const float*)d_in[12];
    const float* wgt_d    = (const float*)d_in[13];
    const float* gruw_d   = (const float*)d_in[14];
    const float* grub_d   = (const float*)d_in[15];
    const float* gam_d    = (const float*)d_in[16];
    float* out = (float*)d_out;

    cudaFuncSetAttribute(conv_mma_kernel,
                         cudaFuncAttributeMaxDynamicSharedMemorySize, CONV_SMEM);

    wt_prep_kernel<<<(2*4*9*128*512 + 255) / 256, 256>>>(ppm_w_r, ppm_w_d);
    gwh_prep_kernel<<<(2*3*128*256 + 255) / 256, 256>>>(gruw_r, gruw_d);
    in_prep_kernel<<<(4*64*NPOS + 255) / 256, 256>>>(feat_rgb, feat_dep);
    conv_mma_kernel<<<dim3(48, 8), 256, CONV_SMEM>>>(ppm_s_r, ppm_b_r,
                                                     ppm_s_d, ppm_b_d, out);
    pa_kernel<<<288, 256>>>(out, pa_w);
    for (int it = 0; it < 2; it++) {
        g1a_kernel<<<dim3(36, 2, 2), 256>>>(out, it, wgt_r, wgt_d);
        g1b_kernel<<<dim3(1152, 2, 2), 256>>>(out, it);
        g2_mma_kernel<<<dim3(24, 2, 16), 256>>>(out, it, grub_r, grub_d);
        g3_mma_kernel<<<dim3(24, 1, 16), 256>>>(out, it, grub_r, grub_d,
                                                gam_r, gam_d);
    }
}

// round 14
// speedup vs baseline: 1.1667x; 1.1667x over previous
#include <cuda_runtime.h>
#include <cuda_fp16.h>
#include <math.h>
#include <stdint.h>

#define NPOS 2304
#define FEATSZ (2*2*4*128*NPOS)

// Scratch
__device__ float  g_feat2[FEATSZ];
__device__ float  g_m[FEATSZ];
__device__ float  g_z[FEATSZ];
__device__ float  g_r[FEATSZ];
__device__ __half g_wth[2*4*9*128*512];  // conv weights [mn][tap][co][ci], fp16
__device__ __half g_gwh[2*3*128*256];    // gru weights  [mod][gate][o][k], fp16
__device__ __half g_inh[2*2*64*NPOS*8];  // conv input   [mb][cg][pos][8ci], fp16
__device__ float  g_gate[2*2*12*NPOS];   // edge gates   [modb][i*3+k][pos]

__device__ __forceinline__ float sigm(float x) { return 1.f / (1.f + expf(-x)); }

__device__ __forceinline__ void mma_f16(float* c, const uint32_t* a, const uint32_t* b) {
    asm volatile(
        "mma.sync.aligned.m16n8k16.row.col.f32.f16.f16.f32 "
        "{%0,%1,%2,%3}, {%4,%5,%6,%7}, {%8,%9}, {%0,%1,%2,%3};"
        : "+f"(c[0]), "+f"(c[1]), "+f"(c[2]), "+f"(c[3])
        : "r"(a[0]), "r"(a[1]), "r"(a[2]), "r"(a[3]), "r"(b[0]), "r"(b[1]));
}

__device__ __forceinline__ void ldsm_x4(uint32_t* r, uint32_t addr) {
    asm volatile("ldmatrix.sync.aligned.m8n8.x4.shared.b16 {%0,%1,%2,%3}, [%4];"
        : "=r"(r[0]), "=r"(r[1]), "=r"(r[2]), "=r"(r[3]) : "r"(addr));
}

#define CPA16(dst, src) \
    asm volatile("cp.async.cg.shared.global [%0], [%1], 16;" :: "r"(dst), "l"(src))
#define CPA16Z(dst, src, nbytes) \
    asm volatile("cp.async.cg.shared.global [%0], [%1], 16, %2;" \
                 :: "r"(dst), "l"(src), "r"(nbytes))
#define CPA_COMMIT() asm volatile("cp.async.commit_group;" ::: "memory")
#define CPA_WAIT1()  asm volatile("cp.async.wait_group 1;" ::: "memory")
#define CPA_WAIT0()  asm volatile("cp.async.wait_group 0;" ::: "memory")

// ---------------------------------------------------------------------------
// Prep kernels
// ---------------------------------------------------------------------------
__global__ void wt_prep_kernel(const float* __restrict__ wR, const float* __restrict__ wD)
{
    int e = blockIdx.x * 256 + threadIdx.x;
    if (e >= 2*4*9*128*512) return;
    int ci = e & 511;
    int r = e >> 9;
    int co = r & 127; r >>= 7;
    int tap = r % 9; r /= 9;
    int node = r & 3;
    int mod = r >> 2;
    const float* w = mod ? wD : wR;
    g_wth[e] = __float2half_rn(w[((size_t)(node*128 + co)*512 + ci)*9 + tap]);
}

__global__ void gwh_prep_kernel(const float* __restrict__ gwR, const float* __restrict__ gwD)
{
    int e = blockIdx.x * 256 + threadIdx.x;
    if (e >= 2*3*128*256) return;
    int mod = e / (3*128*256);
    int x   = e % (3*128*256);
    const float* w = mod ? gwD : gwR;
    g_gwh[e] = __float2half_rn(w[x]);
}

// 8-channel group interleave: g_inh[((mb*64 + cg)*NPOS + pos)*8 + j], ci = cg*8+j
__global__ void in_prep_kernel(const float* __restrict__ inR, const float* __restrict__ inD)
{
    int e = blockIdx.x * 256 + threadIdx.x;
    if (e >= 4 * 64 * NPOS) return;
    int pos = e % NPOS;
    int r = e / NPOS;
    int cg = r & 63;
    int mb = r >> 6;                 // mod*2 + b
    const float* src = ((mb >> 1) ? inD : inR)
                     + ((size_t)(mb & 1) * 512 + cg * 8) * NPOS + pos;
    __half v[8];
#pragma unroll
    for (int j = 0; j < 8; j++) v[j] = __float2half_rn(src[(size_t)j * NPOS]);
    *(uint4*)&g_inh[((size_t)(mb * 64 + cg) * NPOS + pos) * 8] = *(uint4*)v;
}

// ---------------------------------------------------------------------------
// Conv: R10 skeleton (K32, static smem) + 16B cp.async B staging + ldmatrix.
// grid: (48 = b*24 + rowpair, 8 = mod*4+node), 256 threads (8 warps: 4m x 2n)
// ---------------------------------------------------------------------------
#define PH 40
#define A_BUF_H (128*PH)
#define B_BUF_H (96*PH)

__global__ __launch_bounds__(256)
void conv_mma_kernel(const float* __restrict__ sR, const float* __restrict__ bR,
                     const float* __restrict__ sD, const float* __restrict__ bD,
                     float* __restrict__ out)
{
    __shared__ __half smA[2][A_BUF_H];
    __shared__ __half smB[2][B_BUF_H];

    const int tid = threadIdx.x;
    const int lane = tid & 31;
    const int wid = tid >> 5;
    const int wm = wid & 3;
    const int wn = wid >> 2;

    const int mn   = blockIdx.y;
    const int mod  = mn >> 2, node = mn & 3;
    const int dil  = 1 << node;
    const int b    = blockIdx.x / 24;
    const int y0   = (blockIdx.x % 24) * 2;

    const __half* __restrict__ inh = g_inh + (size_t)(mod * 2 + b) * 64 * NPOS * 8;
    const __half* __restrict__ Wt  = g_wth + (size_t)mn * 9 * 128 * 512;

    const int arow = tid >> 1;             // 0..127
    const int ahb  = (tid & 1) * 16;       // halves

    const uint32_t smA0 = (uint32_t)__cvta_generic_to_shared(&smA[0][0]);
    const uint32_t smB0 = (uint32_t)__cvta_generic_to_shared(&smB[0][0]);

    float acc[2][6][4];
#pragma unroll
    for (int i = 0; i < 2; i++)
#pragma unroll
        for (int j = 0; j < 6; j++)
#pragma unroll
            for (int k = 0; k < 4; k++) acc[i][j][k] = 0.f;

#define STAGE(S, BUF) do {                                                    \
    int tap_ = (S) >> 4;                                                      \
    int cc_  = ((S) & 15) * 32;                                               \
    int dy_  = (tap_ / 3 - 1) * dil;                                          \
    int dx_  = (tap_ % 3 - 1) * dil;                                          \
    { const __half* wsrc = Wt + ((size_t)(tap_ * 128) + arow) * 512 + cc_ + ahb; \
      uint32_t ad = smA0 + (uint32_t)(BUF) * (A_BUF_H * 2)                    \
                  + (uint32_t)(arow * PH + ahb) * 2;                          \
      CPA16(ad, wsrc); CPA16(ad + 16, wsrc + 8); }                            \
    _Pragma("unroll")                                                         \
    for (int i = 0; i < 2; i++) {                                             \
        int t = tid + 256 * i;                                                \
        if (t < 384) {                                                        \
            int cgl  = t / 96;                                                \
            int posl = t - cgl * 96;                                          \
            int ry = posl / 48;                                               \
            int x  = posl - ry * 48;                                          \
            int xs = x + dx_, ys = y0 + ry + dy_;                             \
            bool ok = ((unsigned)xs < 48u) && ((unsigned)ys < 48u);           \
            int goff = ok ? (ys * 48 + xs) : 0;                               \
            uint32_t nb = ok ? 16u : 0u;                                      \
            const __half* src = inh + ((size_t)((cc_ >> 3) + cgl) * NPOS + goff) * 8; \
            uint32_t bd = smB0 + (uint32_t)(BUF) * (B_BUF_H * 2)              \
                        + (uint32_t)(posl * PH + cgl * 8) * 2;                \
            CPA16Z(bd, src, nb);                                              \
        }                                                                     \
    }                                                                         \
    CPA_COMMIT();                                                             \
} while (0)

    STAGE(0, 0);

    const int m0 = wm * 32;
    const int n0 = wn * 48;
    // ldmatrix per-lane address constants
    const int rowA = m0 + (lane & 7) + ((lane >> 3) & 1) * 8;
    const int kA   = (lane >> 4) * 8;
    const int rowB = n0 + (lane >> 4) * 8 + (lane & 7);
    const int kB   = ((lane >> 3) & 1) * 8;

    for (int s = 0; s < 144; s++) {
        int buf = s & 1;
        if (s + 1 < 144) {
            STAGE(s + 1, buf ^ 1);
            CPA_WAIT1();
        } else {
            CPA_WAIT0();
        }
        __syncthreads();

        const uint32_t aBase = smA0 + buf * (A_BUF_H * 2);
        const uint32_t bBase = smB0 + buf * (B_BUF_H * 2);
#pragma unroll
        for (int k0 = 0; k0 < 32; k0 += 16) {
            uint32_t af[2][4];
#pragma unroll
            for (int mt = 0; mt < 2; mt++)
                ldsm_x4(af[mt], aBase + (uint32_t)((rowA + mt * 16) * PH + k0 + kA) * 2);
            uint32_t bf[6][2];
#pragma unroll
            for (int ntp = 0; ntp < 3; ntp++) {
                uint32_t rr[4];
                ldsm_x4(rr, bBase + (uint32_t)((rowB + ntp * 16) * PH + k0 + kB) * 2);
                bf[2 * ntp][0] = rr[0]; bf[2 * ntp][1] = rr[1];
                bf[2 * ntp + 1][0] = rr[2]; bf[2 * ntp + 1][1] = rr[3];
            }
#pragma unroll
            for (int nt = 0; nt < 6; nt++) {
                mma_f16(acc[0][nt], af[0], bf[nt]);
                mma_f16(acc[1][nt], af[1], bf[nt]);
            }
        }
        __syncthreads();
    }

    const float* sc = (mod ? sD : sR) + node * 128;
    const float* bi = (mod ? bD : bR) + node * 128;
    float* outp = out + ((size_t)((mod * 2 + b) * 4 + node) * 128) * NPOS + y0 * 48;

#pragma unroll
    for (int mt = 0; mt < 2; mt++) {
#pragma unroll
        for (int half = 0; half < 2; half++) {
            int co = m0 + mt * 16 + half * 8 + (lane >> 2);
            float s = __ldg(sc + co), bb = __ldg(bi + co);
            float* orow = outp + (size_t)co * NPOS;
#pragma unroll
            for (int nt = 0; nt < 6; nt++) {
                int pos = n0 + nt * 8 + (lane & 3) * 2;
                float v0 = fmaxf(fmaf(acc[mt][nt][half * 2 + 0], s, bb), 0.f);
                float v1 = fmaxf(fmaf(acc[mt][nt][half * 2 + 1], s, bb), 0.f);
                *(float2*)(orow + pos) = make_float2(v0, v1);
            }
        }
    }
#undef STAGE
}

// ---------------------------------------------------------------------------
// PA: register-resident cross-modal gating (proven)
// ---------------------------------------------------------------------------
__global__ __launch_bounds__(256)
void pa_kernel(float* __restrict__ feat, const float* __restrict__ paw)
{
    const int pl = threadIdx.x & 63;
    const int cs = threadIdx.x >> 6;
    const int bn  = blockIdx.x / 36;
    const int pos = (blockIdx.x % 36) * 64 + pl;
    float* pr = feat + (size_t)bn * 128 * NPOS + pos;
    float* pd = feat + (size_t)(8 + bn) * 128 * NPOS + pos;

    float r[32], d[32];
#pragma unroll 8
    for (int j = 0; j < 32; j++) {
        int c = cs * 32 + j;
        r[j] = pr[(size_t)c * NPOS];
        d[j] = pd[(size_t)c * NPOS];
    }

    __shared__ float red[2][4][2][64];

#pragma unroll
    for (int it = 0; it < 2; it++) {
        float s0 = 0.f, s1 = 0.f;
#pragma unroll 8
        for (int j = 0; j < 32; j++) {
            int c = cs * 32 + j;
            float df = r[j] - d[j];
            s0 = fmaf(df,  __ldg(paw + c),       s0);
            s1 = fmaf(-df, __ldg(paw + 128 + c), s1);
        }
        red[it][cs][0][pl] = s0;
        red[it][cs][1][pl] = s1;
        __syncthreads();
        float S0 = red[it][0][0][pl] + red[it][1][0][pl] + red[it][2][0][pl] + red[it][3][0][pl];
        float S1 = red[it][0][1][pl] + red[it][1][1][pl] + red[it][2][1][pl] + red[it][3][1][pl];
        float g0 = sigm(S0), g1 = sigm(S1);
#pragma unroll 8
        for (int j = 0; j < 32; j++) {
            float t = r[j];
            r[j] = fmaf(d[j], g1, t);
            d[j] = fmaf(t, g0, d[j]);
        }
    }

#pragma unroll 8
    for (int j = 0; j < 32; j++) {
        int c = cs * 32 + j;
        pr[(size_t)c * NPOS] = r[j];
        pd[(size_t)c * NPOS] = d[j];
    }
}

// ---------------------------------------------------------------------------
// g1a: edge gates (proven)
// ---------------------------------------------------------------------------
__global__ __launch_bounds__(256)
void g1a_kernel(const float* __restrict__ dout, int it,
                const float* __restrict__ wgtR, const float* __restrict__ wgtD)
{
    const float* feat = it ? g_feat2 : dout;
    const int pl = threadIdx.x & 63;
    const int cs = threadIdx.x >> 6;
    const int pos = blockIdx.x * 64 + pl;
    const int b = blockIdx.y, mod = blockIdx.z;
    const float* wgt = mod ? wgtD : wgtR;
    const int modb = mod * 2 + b;
    size_t base = (size_t)(modb * 4) * 128 * NPOS;
    const float* f = feat + base + pos;

    float s[3][4];
#pragma unroll
    for (int k = 0; k < 3; k++)
#pragma unroll
        for (int p = 0; p < 4; p++) s[k][p] = 0.f;

#pragma unroll 4
    for (int j = 0; j < 32; j++) {
        int c = cs * 32 + j;
        float w0 = __ldg(wgt + c), w1 = __ldg(wgt + 128 + c), w2 = __ldg(wgt + 256 + c);
#pragma unroll
        for (int p = 0; p < 4; p++) {
            float fv = f[(size_t)(p * 128 + c) * NPOS];
            s[0][p] = fmaf(w0, fv, s[0][p]);
            s[1][p] = fmaf(w1, fv, s[1][p]);
            s[2][p] = fmaf(w2, fv, s[2][p]);
        }
    }

    __shared__ float red[4][12][64];
#pragma unroll
    for (int k = 0; k < 3; k++)
#pragma unroll
        for (int p = 0; p < 4; p++)
            red[cs][k * 4 + p][pl] = s[k][p];
    __syncthreads();

    if (threadIdx.x < 64) {
        float ss[12];
#pragma unroll
        for (int j = 0; j < 12; j++)
            ss[j] = red[0][j][pl] + red[1][j][pl] + red[2][j][pl] + red[3][j][pl];

        const int OI[4][3] = {{1,2,3},{0,2,3},{0,1,3},{0,1,2}};
#pragma unroll
        for (int i = 0; i < 4; i++)
#pragma unroll
            for (int k = 0; k < 3; k++) {
                float sg = sigm(ss[k * 4 + i] - ss[k * 4 + OI[i][k]]);
                g_gate[(size_t)(modb * 12 + i * 3 + k) * NPOS + pos] = sg;
            }
    }
}

// ---------------------------------------------------------------------------
// g1b: messages (proven)
// ---------------------------------------------------------------------------
__global__ __launch_bounds__(256)
void g1b_kernel(const float* __restrict__ dout, int it)
{
    const float* feat = it ? g_feat2 : dout;
    const int c   = blockIdx.x / 9;
    const int pos = (blockIdx.x % 9) * 256 + threadIdx.x;
    const int b = blockIdx.y, mod = blockIdx.z;
    const int modb = mod * 2 + b;
    size_t base = (size_t)(modb * 4) * 128 * NPOS;
    const float* f = feat + base + (size_t)c * NPOS + pos;

    float fv[4];
#pragma unroll
    for (int p = 0; p < 4; p++) fv[p] = f[(size_t)(p * 128) * NPOS];

    float sg[12];
#pragma unroll
    for (int g = 0; g < 12; g++)
        sg[g] = g_gate[(size_t)(modb * 12 + g) * NPOS + pos];

    const int OI[4][3] = {{1,2,3},{0,2,3},{0,1,3},{0,1,2}};
    const int c3 = c % 3;
    float* mo = g_m + base + (size_t)c * NPOS + pos;
#pragma unroll
    for (int i = 0; i < 4; i++) {
        float msum = 0.f;
#pragma unroll
        for (int k = 0; k < 3; k++) {
            int gi = 2 * k + c3;
            if (gi >= 3) gi -= 3;
            if (gi >= 3) gi -= 3;
            msum = fmaf(fv[OI[i][k]], sg[i * 3 + gi], msum);
        }
        mo[(size_t)(i * 128) * NPOS] = msum;
    }
}

// ---------------------------------------------------------------------------
// g2 via mma.sync fp16 + ldmatrix
// ---------------------------------------------------------------------------
__global__ __launch_bounds__(256)
void g2_mma_kernel(const float* __restrict__ dout, int it,
                   const float* __restrict__ gbR, const float* __restrict__ gbD)
{
    __shared__ __half smA[2][A_BUF_H];
    __shared__ __half smB[2][B_BUF_H];

    const float* feat = it ? g_feat2 : dout;
    const int tid = threadIdx.x;
    const int lane = tid & 31;
    const int wid = tid >> 5;
    const int wm = wid & 3;
    const int wn = wid >> 2;

    const int zid = blockIdx.z;
    const int mod = zid >> 3, bn = zid & 7;
    const int oblk = blockIdx.y;
    const int col0 = blockIdx.x * 96;

    const __half* Agw = g_gwh + (size_t)mod * 3 * 128 * 256 + (size_t)oblk * 128 * 256;
    const float* bias = (mod ? gbD : gbR) + oblk * 128;
    size_t base = (size_t)(mod * 8 + bn) * 128 * NPOS;
    const float* F = feat + base;
    const float* M = g_m + base;

    const int arow = tid >> 1;
    const int ahb  = (tid & 1) * 16;

    const uint32_t smA0 = (uint32_t)__cvta_generic_to_shared(&smA[0][0]);
    const uint32_t smB0 = (uint32_t)__cvta_generic_to_shared(&smB[0][0]);

    float acc[2][6][4];
#pragma unroll
    for (int i = 0; i < 2; i++)
#pragma unroll
        for (int j = 0; j < 6; j++)
#pragma unroll
            for (int k = 0; k < 4; k++) acc[i][j][k] = 0.f;

#define GSTAGE(S, BUF) do {                                                   \
    int cc_ = (S) * 32;                                                       \
    { const __half* wsrc = Agw + (size_t)arow * 256 + cc_ + ahb;              \
      uint4 v0 = *(const uint4*)(wsrc);                                       \
      uint4 v1 = *(const uint4*)(wsrc + 8);                                   \
      __half* ad = &smA[BUF][arow * PH + ahb];                                \
      *(uint4*)(ad) = v0; *(uint4*)(ad + 8) = v1; }                           \
    _Pragma("unroll")                                                         \
    for (int pb = 0; pb < 3; pb++) {                                          \
        int col = lane + 32 * pb;                                             \
        _Pragma("unroll")                                                     \
        for (int pp = 0; pp < 2; pp++) {                                      \
            int x = cc_ + 2 * (wid + 8 * pp);                                 \
            float v0, v1;                                                     \
            if (x < 128) {                                                    \
                v0 = M[(size_t)x * NPOS + col0 + col];                        \
                v1 = M[(size_t)(x + 1) * NPOS + col0 + col];                  \
            } else {                                                          \
                v0 = F[(size_t)(x - 128) * NPOS + col0 + col];                \
                v1 = F[(size_t)(x - 127) * NPOS + col0 + col];                \
            }                                                                 \
            *(half2*)&smB[BUF][col * PH + (x - cc_)] = __floats2half2_rn(v0, v1); \
        }                                                                     \
    }                                                                         \
} while (0)

    GSTAGE(0, 0);
    __syncthreads();

    const int m0 = wm * 32;
    const int n0 = wn * 48;
    const int rowA = m0 + (lane & 7) + ((lane >> 3) & 1) * 8;
    const int kA   = (lane >> 4) * 8;
    const int rowB = n0 + (lane >> 4) * 8 + (lane & 7);
    const int kB   = ((lane >> 3) & 1) * 8;

    for (int s = 0; s < 8; s++) {
        int buf = s & 1;
        if (s + 1 < 8) GSTAGE(s + 1, buf ^ 1);

        const uint32_t aBase = smA0 + buf * (A_BUF_H * 2);
        const uint32_t bBase = smB0 + buf * (B_BUF_H * 2);
#pragma unroll
        for (int k0 = 0; k0 < 32; k0 += 16) {
            uint32_t af[2][4];
#pragma unroll
            for (int mt = 0; mt < 2; mt++)
                ldsm_x4(af[mt], aBase + (uint32_t)((rowA + mt * 16) * PH + k0 + kA) * 2);
            uint32_t bf[6][2];
#pragma unroll
            for (int ntp = 0; ntp < 3; ntp++) {
                uint32_t rr[4];
                ldsm_x4(rr, bBase + (uint32_t)((rowB + ntp * 16) * PH + k0 + kB) * 2);
                bf[2 * ntp][0] = rr[0]; bf[2 * ntp][1] = rr[1];
                bf[2 * ntp + 1][0] = rr[2]; bf[2 * ntp + 1][1] = rr[3];
            }
#pragma unroll
            for (int nt = 0; nt < 6; nt++) {
                mma_f16(acc[0][nt], af[0], bf[nt]);
                mma_f16(acc[1][nt], af[1], bf[nt]);
            }
        }
        __syncthreads();
    }

    float* ob = (oblk == 0) ? (g_z + base) : (g_r + base);
#pragma unroll
    for (int mt = 0; mt < 2; mt++) {
#pragma unroll
        for (int half = 0; half < 2; half++) {
            int o = m0 + mt * 16 + half * 8 + (lane >> 2);
            float bv = __ldg(bias + o);
            float* orow = ob + (size_t)o * NPOS + col0;
#pragma unroll
            for (int nt = 0; nt < 6; nt++) {
                int col = n0 + nt * 8 + (lane & 3) * 2;
                orow[col]     = sigm(acc[mt][nt][half * 2 + 0] + bv);
                orow[col + 1] = sigm(acc[mt][nt][half * 2 + 1] + bv);
            }
        }
    }
#undef GSTAGE
}

// ---------------------------------------------------------------------------
// g3 via mma.sync fp16 + ldmatrix, fused GRU update
// ---------------------------------------------------------------------------
__global__ __launch_bounds__(256)
void g3_mma_kernel(float* __restrict__ dout, int it,
                   const float* __restrict__ gbR, const float* __restrict__ gbD,
                   const float* __restrict__ gamR, const float* __restrict__ gamD)
{
    __shared__ __half smA[2][A_BUF_H];
    __shared__ __half smB[2][B_BUF_H];

    const float* feat = it ? g_feat2 : dout;
    float* dst        = it ? dout : g_feat2;
    const int tid = threadIdx.x;
    const int lane = tid & 31;
    const int wid = tid >> 5;
    const int wm = wid & 3;
    const int wn = wid >> 2;

    const int zid = blockIdx.z;
    const int mod = zid >> 3, bn = zid & 7;
    const int col0 = blockIdx.x * 96;

    const __half* Agw = g_gwh + (size_t)mod * 3 * 128 * 256 + (size_t)2 * 128 * 256;
    const float* bias = (mod ? gbD : gbR) + 2 * 128;
    float gam = mod ? __ldg(gamD) : __ldg(gamR);
    size_t base = (size_t)(mod * 8 + bn) * 128 * NPOS;
    const float* F = feat + base;
    const float* M = g_m + base;
    const float* R = g_r + base;

    const int arow = tid >> 1;
    const int ahb  = (tid & 1) * 16;

    const uint32_t smA0 = (uint32_t)__cvta_generic_to_shared(&smA[0][0]);
    const uint32_t smB0 = (uint32_t)__cvta_generic_to_shared(&smB[0][0]);

    float acc[2][6][4];
#pragma unroll
    for (int i = 0; i < 2; i++)
#pragma unroll
        for (int j = 0; j < 6; j++)
#pragma unroll
            for (int k = 0; k < 4; k++) acc[i][j][k] = 0.f;

#define G3STAGE(S, BUF) do {                                                  \
    int cc_ = (S) * 32;                                                       \
    { const __half* wsrc = Agw + (size_t)arow * 256 + cc_ + ahb;              \
      uint4 v0 = *(const uint4*)(wsrc);                                       \
      uint4 v1 = *(const uint4*)(wsrc + 8);                                   \
      __half* ad = &smA[BUF][arow * PH + ahb];                                \
      *(uint4*)(ad) = v0; *(uint4*)(ad + 8) = v1; }                           \
    _Pragma("unroll")                                                         \
    for (int pb = 0; pb < 3; pb++) {                                          \
        int col = lane + 32 * pb;                                             \
        _Pragma("unroll")                                                     \
        for (int pp = 0; pp < 2; pp++) {                                      \
            int x = cc_ + 2 * (wid + 8 * pp);                                 \
            float v0, v1;                                                     \
            if (x < 128) {                                                    \
                v0 = M[(size_t)x * NPOS + col0 + col];                        \
                v1 = M[(size_t)(x + 1) * NPOS + col0 + col];                  \
            } else {                                                          \
                size_t i0 = (size_t)(x - 128) * NPOS + col0 + col;            \
                size_t i1 = (size_t)(x - 127) * NPOS + col0 + col;            \
                v0 = F[i0] * R[i0];                                           \
                v1 = F[i1] * R[i1];                                           \
            }                                                                 \
            *(half2*)&smB[BUF][col * PH + (x - cc_)] = __floats2half2_rn(v0, v1); \
        }                                                                     \
    }                                                                         \
} while (0)

    G3STAGE(0, 0);
    __syncthreads();

    const int m0 = wm * 32;
    const int n0 = wn * 48;
    const int rowA = m0 + (lane & 7) + ((lane >> 3) & 1) * 8;
    const int kA   = (lane >> 4) * 8;
    const int rowB = n0 + (lane >> 4) * 8 + (lane & 7);
    const int kB   = ((lane >> 3) & 1) * 8;

    for (int s = 0; s < 8; s++) {
        int buf = s & 1;
        if (s + 1 < 8) G3STAGE(s + 1, buf ^ 1);

        const uint32_t aBase = smA0 + buf * (A_BUF_H * 2);
        const uint32_t bBase = smB0 + buf * (B_BUF_H * 2);
#pragma unroll
        for (int k0 = 0; k0 < 32; k0 += 16) {
            uint32_t af[2][4];
#pragma unroll
            for (int mt = 0; mt < 2; mt++)
                ldsm_x4(af[mt], aBase + (uint32_t)((rowA + mt * 16) * PH + k0 + kA) * 2);
            uint32_t bf[6][2];
#pragma unroll
            for (int ntp = 0; ntp < 3; ntp++) {
                uint32_t rr[4];
                ldsm_x4(rr, bBase + (uint32_t)((rowB + ntp * 16) * PH + k0 + kB) * 2);
                bf[2 * ntp][0] = rr[0]; bf[2 * ntp][1] = rr[1];
                bf[2 * ntp + 1][0] = rr[2]; bf[2 * ntp + 1][1] = rr[3];
            }
#pragma unroll
            for (int nt = 0; nt < 6; nt++) {
                mma_f16(acc[0][nt], af[0], bf[nt]);
                mma_f16(acc[1][nt], af[1], bf[nt]);
            }
        }
        __syncthreads();
    }

#pragma unroll
    for (int mt = 0; mt < 2; mt++) {
#pragma unroll
        for (int half = 0; half < 2; half++) {
            int o = m0 + mt * 16 + half * 8 + (lane >> 2);
            float bv = __ldg(bias + o);
#pragma unroll
            for (int nt = 0; nt < 6; nt++) {
                int col = col0 + n0 + nt * 8 + (lane & 3) * 2;
#pragma unroll
                for (int u = 0; u < 2; u++) {
                    size_t idx = base + (size_t)o * NPOS + col + u;
                    float cand = tanhf(acc[mt][nt][half * 2 + u] + bv);
                    float z = g_z[idx];
                    float f = feat[idx];
                    dst[idx] = fmaf(gam, fmaf(f, 1.f - z, cand * z), f);
                }
            }
        }
    }
#undef G3STAGE
}

// ---------------------------------------------------------------------------
extern "C" void kernel_launch(void* const* d_in, const int* in_sizes, int n_in,
                              void* d_out, int out_size)
{
    const float* feat_rgb = (const float*)d_in[0];
    const float* feat_dep = (const float*)d_in[1];
    const float* ppm_w_r  = (const float*)d_in[2];
    const float* ppm_s_r  = (const float*)d_in[3];
    const float* ppm_b_r  = (const float*)d_in[4];
    const float* ppm_w_d  = (const float*)d_in[5];
    const float* ppm_s_d  = (const float*)d_in[6];
    const float* ppm_b_d  = (const float*)d_in[7];
    const float* pa_w     = (const float*)d_in[8];
    const float* wgt_r    = (const float*)d_in[9];
    const float* gruw_r   = (const float*)d_in[10];
    const float* grub_r   = (const float*)d_in[11];
    const float* gam_r    = (const float*)d_in[12];
    const float* wgt_d    = (const float*)d_in[13];
    const float* gruw_d   = (const float*)d_in[14];
    const float* grub_d   = (const float*)d_in[15];
    const float* gam_d    = (const float*)d_in[16];
    float* out = (float*)d_out;

    wt_prep_kernel<<<(2*4*9*128*512 + 255) / 256, 256>>>(ppm_w_r, ppm_w_d);
    gwh_prep_kernel<<<(2*3*128*256 + 255) / 256, 256>>>(gruw_r, gruw_d);
    in_prep_kernel<<<(4*64*NPOS + 255) / 256, 256>>>(feat_rgb, feat_dep);
    conv_mma_kernel<<<dim3(48, 8), 256>>>(ppm_s_r, ppm_b_r, ppm_s_d, ppm_b_d, out);
    pa_kernel<<<288, 256>>>(out, pa_w);
    for (int it = 0; it < 2; it++) {
        g1a_kernel<<<dim3(36, 2, 2), 256>>>(out, it, wgt_r, wgt_d);
        g1b_kernel<<<dim3(1152, 2, 2), 256>>>(out, it);
        g2_mma_kernel<<<dim3(24, 2, 16), 256>>>(out, it, grub_r, grub_d);
        g3_mma_kernel<<<dim3(24, 1, 16), 256>>>(out, it, grub_r, grub_d,
                                                gam_r, gam_d);
    }
}

// round 16
// speedup vs baseline: 1.1785x; 1.0101x over previous
#include <cuda_runtime.h>
#include <cuda_fp16.h>
#include <math.h>
#include <stdint.h>

#define NPOS 2304
#define FEATSZ (2*2*4*128*NPOS)

// Scratch
__device__ float  g_feat2[FEATSZ];
__device__ float  g_m[FEATSZ];
__device__ float  g_z[FEATSZ];
__device__ float  g_r[FEATSZ];
__device__ __half g_wth[2*4*9*128*512];  // conv weights [mn][tap][co][ci], fp16
__device__ __half g_gwh[2*3*128*256];    // gru weights  [mod][gate][o][k], fp16
__device__ __half g_inh[2*2*64*NPOS*8];  // conv input   [mb][cg][pos][8ci], fp16
__device__ float  g_gate[2*2*12*NPOS];   // edge gates   [modb][i*3+k][pos]

__device__ __forceinline__ float sigm(float x) { return 1.f / (1.f + expf(-x)); }

__device__ __forceinline__ void mma_f16(float* c, const uint32_t* a, const uint32_t* b) {
    asm volatile(
        "mma.sync.aligned.m16n8k16.row.col.f32.f16.f16.f32 "
        "{%0,%1,%2,%3}, {%4,%5,%6,%7}, {%8,%9}, {%0,%1,%2,%3};"
        : "+f"(c[0]), "+f"(c[1]), "+f"(c[2]), "+f"(c[3])
        : "r"(a[0]), "r"(a[1]), "r"(a[2]), "r"(a[3]), "r"(b[0]), "r"(b[1]));
}

__device__ __forceinline__ void ldsm_x4(uint32_t* r, uint32_t addr) {
    asm volatile("ldmatrix.sync.aligned.m8n8.x4.shared.b16 {%0,%1,%2,%3}, [%4];"
        : "=r"(r[0]), "=r"(r[1]), "=r"(r[2]), "=r"(r[3]) : "r"(addr));
}

#define CPA16(dst, src) \
    asm volatile("cp.async.cg.shared.global [%0], [%1], 16;" :: "r"(dst), "l"(src))
#define CPA16Z(dst, src, nbytes) \
    asm volatile("cp.async.cg.shared.global [%0], [%1], 16, %2;" \
                 :: "r"(dst), "l"(src), "r"(nbytes))
#define CPA_COMMIT() asm volatile("cp.async.commit_group;" ::: "memory")
#define CPA_WAIT1()  asm volatile("cp.async.wait_group 1;" ::: "memory")
#define CPA_WAIT0()  asm volatile("cp.async.wait_group 0;" ::: "memory")

// ---------------------------------------------------------------------------
// Prep kernels
// ---------------------------------------------------------------------------
__global__ void wt_prep_kernel(const float* __restrict__ wR, const float* __restrict__ wD)
{
    int e = blockIdx.x * 256 + threadIdx.x;
    if (e >= 2*4*9*128*512) return;
    int ci = e & 511;
    int r = e >> 9;
    int co = r & 127; r >>= 7;
    int tap = r % 9; r /= 9;
    int node = r & 3;
    int mod = r >> 2;
    const float* w = mod ? wD : wR;
    g_wth[e] = __float2half_rn(w[((size_t)(node*128 + co)*512 + ci)*9 + tap]);
}

__global__ void gwh_prep_kernel(const float* __restrict__ gwR, const float* __restrict__ gwD)
{
    int e = blockIdx.x * 256 + threadIdx.x;
    if (e >= 2*3*128*256) return;
    int mod = e / (3*128*256);
    int x   = e % (3*128*256);
    const float* w = mod ? gwD : gwR;
    g_gwh[e] = __float2half_rn(w[x]);
}

// 8-channel group interleave: g_inh[((mb*64 + cg)*NPOS + pos)*8 + j], ci = cg*8+j
__global__ void in_prep_kernel(const float* __restrict__ inR, const float* __restrict__ inD)
{
    int e = blockIdx.x * 256 + threadIdx.x;
    if (e >= 4 * 64 * NPOS) return;
    int pos = e % NPOS;
    int r = e / NPOS;
    int cg = r & 63;
    int mb = r >> 6;                 // mod*2 + b
    const float* src = ((mb >> 1) ? inD : inR)
                     + ((size_t)(mb & 1) * 512 + cg * 8) * NPOS + pos;
    __half v[8];
#pragma unroll
    for (int j = 0; j < 8; j++) v[j] = __float2half_rn(src[(size_t)j * NPOS]);
    *(uint4*)&g_inh[((size_t)(mb * 64 + cg) * NPOS + pos) * 8] = *(uint4*)v;
}

// ---------------------------------------------------------------------------
// Conv: K32 + 16B cp.async B staging + ldmatrix + 3-slot ring, 1 barrier/stage.
// Dynamic smem (53.8 KB). grid: (48, 8), 256 threads (8 warps: 4m x 2n)
// ---------------------------------------------------------------------------
#define PH 40
#define A_BUF_H (128*PH)
#define B_BUF_H (96*PH)
#define SLOT_H (A_BUF_H + B_BUF_H)              // halves per slot
#define CONV_SMEM (3 * SLOT_H * 2)              // bytes

__global__ __launch_bounds__(256)
void conv_mma_kernel(const float* __restrict__ sR, const float* __restrict__ bR,
                     const float* __restrict__ sD, const float* __restrict__ bD,
                     float* __restrict__ out)
{
    extern __shared__ __half csm[];   // [3][A_BUF_H + B_BUF_H]

    const int tid = threadIdx.x;
    const int lane = tid & 31;
    const int wid = tid >> 5;
    const int wm = wid & 3;
    const int wn = wid >> 2;

    const int mn   = blockIdx.y;
    const int mod  = mn >> 2, node = mn & 3;
    const int dil  = 1 << node;
    const int b    = blockIdx.x / 24;
    const int y0   = (blockIdx.x % 24) * 2;

    const __half* __restrict__ inh = g_inh + (size_t)(mod * 2 + b) * 64 * NPOS * 8;
    const __half* __restrict__ Wt  = g_wth + (size_t)mn * 9 * 128 * 512;

    const int arow = tid >> 1;             // 0..127
    const int ahb  = (tid & 1) * 16;       // halves

    const uint32_t smBase = (uint32_t)__cvta_generic_to_shared(csm);
    // slot layout: A at slot*SLOT_H, B at slot*SLOT_H + A_BUF_H (in halves)

    float acc[2][6][4];
#pragma unroll
    for (int i = 0; i < 2; i++)
#pragma unroll
        for (int j = 0; j < 6; j++)
#pragma unroll
            for (int k = 0; k < 4; k++) acc[i][j][k] = 0.f;

#define STAGE(S, BUF) do {                                                    \
    int tap_ = (S) >> 4;                                                      \
    int cc_  = ((S) & 15) * 32;                                               \
    int dy_  = (tap_ / 3 - 1) * dil;                                          \
    int dx_  = (tap_ % 3 - 1) * dil;                                          \
    { const __half* wsrc = Wt + ((size_t)(tap_ * 128) + arow) * 512 + cc_ + ahb; \
      uint32_t ad = smBase + (uint32_t)((BUF) * SLOT_H + arow * PH + ahb) * 2;\
      CPA16(ad, wsrc); CPA16(ad + 16, wsrc + 8); }                            \
    _Pragma("unroll")                                                         \
    for (int i = 0; i < 2; i++) {                                             \
        int t = tid + 256 * i;                                                \
        if (t < 384) {                                                        \
            int cgl  = t / 96;                                                \
            int posl = t - cgl * 96;                                          \
            int ry = posl / 48;                                               \
            int x  = posl - ry * 48;                                          \
            int xs = x + dx_, ys = y0 + ry + dy_;                             \
            bool ok = ((unsigned)xs < 48u) && ((unsigned)ys < 48u);           \
            int goff = ok ? (ys * 48 + xs) : 0;                               \
            uint32_t nb = ok ? 16u : 0u;                                      \
            const __half* src = inh + ((size_t)((cc_ >> 3) + cgl) * NPOS + goff) * 8; \
            uint32_t bd = smBase + (uint32_t)((BUF) * SLOT_H + A_BUF_H        \
                        + posl * PH + cgl * 8) * 2;                           \
            CPA16Z(bd, src, nb);                                              \
        }                                                                     \
    }                                                                         \
    CPA_COMMIT();                                                             \
} while (0)

    STAGE(0, 0);
    STAGE(1, 1);

    const int m0 = wm * 32;
    const int n0 = wn * 48;
    // ldmatrix per-lane address constants
    const int rowA = m0 + (lane & 7) + ((lane >> 3) & 1) * 8;
    const int kA   = (lane >> 4) * 8;
    const int rowB = n0 + (lane >> 4) * 8 + (lane & 7);
    const int kB   = ((lane >> 3) & 1) * 8;

    int slot = 0;          // s % 3
    int nslot = 2;         // (s+2) % 3
    for (int s = 0; s < 144; s++) {
        if (s <= 142) CPA_WAIT1(); else CPA_WAIT0();
        __syncthreads();
        if (s + 2 < 144) STAGE(s + 2, nslot);

        const uint32_t aBase = smBase + (uint32_t)(slot * SLOT_H) * 2;
        const uint32_t bBase = aBase + (uint32_t)A_BUF_H * 2;
#pragma unroll
        for (int k0 = 0; k0 < 32; k0 += 16) {
            uint32_t af[2][4];
#pragma unroll
            for (int mt = 0; mt < 2; mt++)
                ldsm_x4(af[mt], aBase + (uint32_t)((rowA + mt * 16) * PH + k0 + kA) * 2);
            uint32_t bf[6][2];
#pragma unroll
            for (int ntp = 0; ntp < 3; ntp++) {
                uint32_t rr[4];
                ldsm_x4(rr, bBase + (uint32_t)((rowB + ntp * 16) * PH + k0 + kB) * 2);
                bf[2 * ntp][0] = rr[0]; bf[2 * ntp][1] = rr[1];
                bf[2 * ntp + 1][0] = rr[2]; bf[2 * ntp + 1][1] = rr[3];
            }
#pragma unroll
            for (int nt = 0; nt < 6; nt++) {
                mma_f16(acc[0][nt], af[0], bf[nt]);
                mma_f16(acc[1][nt], af[1], bf[nt]);
            }
        }
        slot = (slot == 2) ? 0 : slot + 1;
        nslot = (nslot == 2) ? 0 : nslot + 1;
    }

    const float* sc = (mod ? sD : sR) + node * 128;
    const float* bi = (mod ? bD : bR) + node * 128;
    float* outp = out + ((size_t)((mod * 2 + b) * 4 + node) * 128) * NPOS + y0 * 48;

#pragma unroll
    for (int mt = 0; mt < 2; mt++) {
#pragma unroll
        for (int half = 0; half < 2; half++) {
            int co = m0 + mt * 16 + half * 8 + (lane >> 2);
            float s = __ldg(sc + co), bb = __ldg(bi + co);
            float* orow = outp + (size_t)co * NPOS;
#pragma unroll
            for (int nt = 0; nt < 6; nt++) {
                int pos = n0 + nt * 8 + (lane & 3) * 2;
                float v0 = fmaxf(fmaf(acc[mt][nt][half * 2 + 0], s, bb), 0.f);
                float v1 = fmaxf(fmaf(acc[mt][nt][half * 2 + 1], s, bb), 0.f);
                *(float2*)(orow + pos) = make_float2(v0, v1);
            }
        }
    }
#undef STAGE
}

// ---------------------------------------------------------------------------
// PA: register-resident cross-modal gating (proven)
// ---------------------------------------------------------------------------
__global__ __launch_bounds__(256)
void pa_kernel(float* __restrict__ feat, const float* __restrict__ paw)
{
    const int pl = threadIdx.x & 63;
    const int cs = threadIdx.x >> 6;
    const int bn  = blockIdx.x / 36;
    const int pos = (blockIdx.x % 36) * 64 + pl;
    float* pr = feat + (size_t)bn * 128 * NPOS + pos;
    float* pd = feat + (size_t)(8 + bn) * 128 * NPOS + pos;

    float r[32], d[32];
#pragma unroll 8
    for (int j = 0; j < 32; j++) {
        int c = cs * 32 + j;
        r[j] = pr[(size_t)c * NPOS];
        d[j] = pd[(size_t)c * NPOS];
    }

    __shared__ float red[2][4][2][64];

#pragma unroll
    for (int it = 0; it < 2; it++) {
        float s0 = 0.f, s1 = 0.f;
#pragma unroll 8
        for (int j = 0; j < 32; j++) {
            int c = cs * 32 + j;
            float df = r[j] - d[j];
            s0 = fmaf(df,  __ldg(paw + c),       s0);
            s1 = fmaf(-df, __ldg(paw + 128 + c), s1);
        }
        red[it][cs][0][pl] = s0;
        red[it][cs][1][pl] = s1;
        __syncthreads();
        float S0 = red[it][0][0][pl] + red[it][1][0][pl] + red[it][2][0][pl] + red[it][3][0][pl];
        float S1 = red[it][0][1][pl] + red[it][1][1][pl] + red[it][2][1][pl] + red[it][3][1][pl];
        float g0 = sigm(S0), g1 = sigm(S1);
#pragma unroll 8
        for (int j = 0; j < 32; j++) {
            float t = r[j];
            r[j] = fmaf(d[j], g1, t);
            d[j] = fmaf(t, g0, d[j]);
        }
    }

#pragma unroll 8
    for (int j = 0; j < 32; j++) {
        int c = cs * 32 + j;
        pr[(size_t)c * NPOS] = r[j];
        pd[(size_t)c * NPOS] = d[j];
    }
}

// ---------------------------------------------------------------------------
// g1a: edge gates (proven)
// ---------------------------------------------------------------------------
__global__ __launch_bounds__(256)
void g1a_kernel(const float* __restrict__ dout, int it,
                const float* __restrict__ wgtR, const float* __restrict__ wgtD)
{
    const float* feat = it ? g_feat2 : dout;
    const int pl = threadIdx.x & 63;
    const int cs = threadIdx.x >> 6;
    const int pos = blockIdx.x * 64 + pl;
    const int b = blockIdx.y, mod = blockIdx.z;
    const float* wgt = mod ? wgtD : wgtR;
    const int modb = mod * 2 + b;
    size_t base = (size_t)(modb * 4) * 128 * NPOS;
    const float* f = feat + base + pos;

    float s[3][4];
#pragma unroll
    for (int k = 0; k < 3; k++)
#pragma unroll
        for (int p = 0; p < 4; p++) s[k][p] = 0.f;

#pragma unroll 4
    for (int j = 0; j < 32; j++) {
        int c = cs * 32 + j;
        float w0 = __ldg(wgt + c), w1 = __ldg(wgt + 128 + c), w2 = __ldg(wgt + 256 + c);
#pragma unroll
        for (int p = 0; p < 4; p++) {
            float fv = f[(size_t)(p * 128 + c) * NPOS];
            s[0][p] = fmaf(w0, fv, s[0][p]);
            s[1][p] = fmaf(w1, fv, s[1][p]);
            s[2][p] = fmaf(w2, fv, s[2][p]);
        }
    }

    __shared__ float red[4][12][64];
#pragma unroll
    for (int k = 0; k < 3; k++)
#pragma unroll
        for (int p = 0; p < 4; p++)
            red[cs][k * 4 + p][pl] = s[k][p];
    __syncthreads();

    if (threadIdx.x < 64) {
        float ss[12];
#pragma unroll
        for (int j = 0; j < 12; j++)
            ss[j] = red[0][j][pl] + red[1][j][pl] + red[2][j][pl] + red[3][j][pl];

        const int OI[4][3] = {{1,2,3},{0,2,3},{0,1,3},{0,1,2}};
#pragma unroll
        for (int i = 0; i < 4; i++)
#pragma unroll
            for (int k = 0; k < 3; k++) {
                float sg = sigm(ss[k * 4 + i] - ss[k * 4 + OI[i][k]]);
                g_gate[(size_t)(modb * 12 + i * 3 + k) * NPOS + pos] = sg;
            }
    }
}

// ---------------------------------------------------------------------------
// g1b: messages (proven)
// ---------------------------------------------------------------------------
__global__ __launch_bounds__(256)
void g1b_kernel(const float* __restrict__ dout, int it)
{
    const float* feat = it ? g_feat2 : dout;
    const int c   = blockIdx.x / 9;
    const int pos = (blockIdx.x % 9) * 256 + threadIdx.x;
    const int b = blockIdx.y, mod = blockIdx.z;
    const int modb = mod * 2 + b;
    size_t base = (size_t)(modb * 4) * 128 * NPOS;
    const float* f = feat + base + (size_t)c * NPOS + pos;

    float fv[4];
#pragma unroll
    for (int p = 0; p < 4; p++) fv[p] = f[(size_t)(p * 128) * NPOS];

    float sg[12];
#pragma unroll
    for (int g = 0; g < 12; g++)
        sg[g] = g_gate[(size_t)(modb * 12 + g) * NPOS + pos];

    const int OI[4][3] = {{1,2,3},{0,2,3},{0,1,3},{0,1,2}};
    const int c3 = c % 3;
    float* mo = g_m + base + (size_t)c * NPOS + pos;
#pragma unroll
    for (int i = 0; i < 4; i++) {
        float msum = 0.f;
#pragma unroll
        for (int k = 0; k < 3; k++) {
            int gi = 2 * k + c3;
            if (gi >= 3) gi -= 3;
            if (gi >= 3) gi -= 3;
            msum = fmaf(fv[OI[i][k]], sg[i * 3 + gi], msum);
        }
        mo[(size_t)(i * 128) * NPOS] = msum;
    }
}

// ---------------------------------------------------------------------------
// g2 via mma.sync fp16 + ldmatrix (proven at R14)
// ---------------------------------------------------------------------------
__global__ __launch_bounds__(256)
void g2_mma_kernel(const float* __restrict__ dout, int it,
                   const float* __restrict__ gbR, const float* __restrict__ gbD)
{
    __shared__ __half smA[2][A_BUF_H];
    __shared__ __half smB[2][B_BUF_H];

    const float* feat = it ? g_feat2 : dout;
    const int tid = threadIdx.x;
    const int lane = tid & 31;
    const int wid = tid >> 5;
    const int wm = wid & 3;
    const int wn = wid >> 2;

    const int zid = blockIdx.z;
    const int mod = zid >> 3, bn = zid & 7;
    const int oblk = blockIdx.y;
    const int col0 = blockIdx.x * 96;

    const __half* Agw = g_gwh + (size_t)mod * 3 * 128 * 256 + (size_t)oblk * 128 * 256;
    const float* bias = (mod ? gbD : gbR) + oblk * 128;
    size_t base = (size_t)(mod * 8 + bn) * 128 * NPOS;
    const float* F = feat + base;
    const float* M = g_m + base;

    const int arow = tid >> 1;
    const int ahb  = (tid & 1) * 16;

    const uint32_t smA0 = (uint32_t)__cvta_generic_to_shared(&smA[0][0]);
    const uint32_t smB0 = (uint32_t)__cvta_generic_to_shared(&smB[0][0]);

    float acc[2][6][4];
#pragma unroll
    for (int i = 0; i < 2; i++)
#pragma unroll
        for (int j = 0; j < 6; j++)
#pragma unroll
            for (int k = 0; k < 4; k++) acc[i][j][k] = 0.f;

#define GSTAGE(S, BUF) do {                                                   \
    int cc_ = (S) * 32;                                                       \
    { const __half* wsrc = Agw + (size_t)arow * 256 + cc_ + ahb;              \
      uint4 v0 = *(const uint4*)(wsrc);                                       \
      uint4 v1 = *(const uint4*)(wsrc + 8);                                   \
      __half* ad = &smA[BUF][arow * PH + ahb];                                \
      *(uint4*)(ad) = v0; *(uint4*)(ad + 8) = v1; }                           \
    _Pragma("unroll")                                                         \
    for (int pb = 0; pb < 3; pb++) {                                          \
        int col = lane + 32 * pb;                                             \
        _Pragma("unroll")                                                     \
        for (int pp = 0; pp < 2; pp++) {                                      \
            int x = cc_ + 2 * (wid + 8 * pp);                                 \
            float v0, v1;                                                     \
            if (x < 128) {                                                    \
                v0 = M[(size_t)x * NPOS + col0 + col];                        \
                v1 = M[(size_t)(x + 1) * NPOS + col0 + col];                  \
            } else {                                                          \
                v0 = F[(size_t)(x - 128) * NPOS + col0 + col];                \
                v1 = F[(size_t)(x - 127) * NPOS + col0 + col];                \
            }                                                                 \
            *(half2*)&smB[BUF][col * PH + (x - cc_)] = __floats2half2_rn(v0, v1); \
        }                                                                     \
    }                                                                         \
} while (0)

    GSTAGE(0, 0);
    __syncthreads();

    const int m0 = wm * 32;
    const int n0 = wn * 48;
    const int rowA = m0 + (lane & 7) + ((lane >> 3) & 1) * 8;
    const int kA   = (lane >> 4) * 8;
    const int rowB = n0 + (lane >> 4) * 8 + (lane & 7);
    const int kB   = ((lane >> 3) & 1) * 8;

    for (int s = 0; s < 8; s++) {
        int buf = s & 1;
        if (s + 1 < 8) GSTAGE(s + 1, buf ^ 1);

        const uint32_t aBase = smA0 + buf * (A_BUF_H * 2);
        const uint32_t bBase = smB0 + buf * (B_BUF_H * 2);
#pragma unroll
        for (int k0 = 0; k0 < 32; k0 += 16) {
            uint32_t af[2][4];
#pragma unroll
            for (int mt = 0; mt < 2; mt++)
                ldsm_x4(af[mt], aBase + (uint32_t)((rowA + mt * 16) * PH + k0 + kA) * 2);
            uint32_t bf[6][2];
#pragma unroll
            for (int ntp = 0; ntp < 3; ntp++) {
                uint32_t rr[4];
                ldsm_x4(rr, bBase + (uint32_t)((rowB + ntp * 16) * PH + k0 + kB) * 2);
                bf[2 * ntp][0] = rr[0]; bf[2 * ntp][1] = rr[1];
                bf[2 * ntp + 1][0] = rr[2]; bf[2 * ntp + 1][1] = rr[3];
            }
#pragma unroll
            for (int nt = 0; nt < 6; nt++) {
                mma_f16(acc[0][nt], af[0], bf[nt]);
                mma_f16(acc[1][nt], af[1], bf[nt]);
            }
        }
        __syncthreads();
    }

    float* ob = (oblk == 0) ? (g_z + base) : (g_r + base);
#pragma unroll
    for (int mt = 0; mt < 2; mt++) {
#pragma unroll
        for (int half = 0; half < 2; half++) {
            int o = m0 + mt * 16 + half * 8 + (lane >> 2);
            float bv = __ldg(bias + o);
            float* orow = ob + (size_t)o * NPOS + col0;
#pragma unroll
            for (int nt = 0; nt < 6; nt++) {
                int col = n0 + nt * 8 + (lane & 3) * 2;
                orow[col]     = sigm(acc[mt][nt][half * 2 + 0] + bv);
                orow[col + 1] = sigm(acc[mt][nt][half * 2 + 1] + bv);
            }
        }
    }
#undef GSTAGE
}

// ---------------------------------------------------------------------------
// g3 via mma.sync fp16 + ldmatrix, fused GRU update (proven at R14)
// ---------------------------------------------------------------------------
__global__ __launch_bounds__(256)
void g3_mma_kernel(float* __restrict__ dout, int it,
                   const float* __restrict__ gbR, const float* __restrict__ gbD,
                   const float* __restrict__ gamR, const float* __restrict__ gamD)
{
    __shared__ __half smA[2][A_BUF_H];
    __shared__ __half smB[2][B_BUF_H];

    const float* feat = it ? g_feat2 : dout;
    float* dst        = it ? dout : g_feat2;
    const int tid = threadIdx.x;
    const int lane = tid & 31;
    const int wid = tid >> 5;
    const int wm = wid & 3;
    const int wn = wid >> 2;

    const int zid = blockIdx.z;
    const int mod = zid >> 3, bn = zid & 7;
    const int col0 = blockIdx.x * 96;

    const __half* Agw = g_gwh + (size_t)mod * 3 * 128 * 256 + (size_t)2 * 128 * 256;
    const float* bias = (mod ? gbD : gbR) + 2 * 128;
    float gam = mod ? __ldg(gamD) : __ldg(gamR);
    size_t base = (size_t)(mod * 8 + bn) * 128 * NPOS;
    const float* F = feat + base;
    const float* M = g_m + base;
    const float* R = g_r + base;

    const int arow = tid >> 1;
    const int ahb  = (tid & 1) * 16;

    const uint32_t smA0 = (uint32_t)__cvta_generic_to_shared(&smA[0][0]);
    const uint32_t smB0 = (uint32_t)__cvta_generic_to_shared(&smB[0][0]);

    float acc[2][6][4];
#pragma unroll
    for (int i = 0; i < 2; i++)
#pragma unroll
        for (int j = 0; j < 6; j++)
#pragma unroll
            for (int k = 0; k < 4; k++) acc[i][j][k] = 0.f;

#define G3STAGE(S, BUF) do {                                                  \
    int cc_ = (S) * 32;                                                       \
    { const __half* wsrc = Agw + (size_t)arow * 256 + cc_ + ahb;              \
      uint4 v0 = *(const uint4*)(wsrc);                                       \
      uint4 v1 = *(const uint4*)(wsrc + 8);                                   \
      __half* ad = &smA[BUF][arow * PH + ahb];                                \
      *(uint4*)(ad) = v0; *(uint4*)(ad + 8) = v1; }                           \
    _Pragma("unroll")                                                         \
    for (int pb = 0; pb < 3; pb++) {                                          \
        int col = lane + 32 * pb;                                             \
        _Pragma("unroll")                                                     \
        for (int pp = 0; pp < 2; pp++) {                                      \
            int x = cc_ + 2 * (wid + 8 * pp);                                 \
            float v0, v1;                                                     \
            if (x < 128) {                                                    \
                v0 = M[(size_t)x * NPOS + col0 + col];                        \
                v1 = M[(size_t)(x + 1) * NPOS + col0 + col];                  \
            } else {                                                          \
                size_t i0 = (size_t)(x - 128) * NPOS + col0 + col;            \
                size_t i1 = (size_t)(x - 127) * NPOS + col0 + col;            \
                v0 = F[i0] * R[i0];                                           \
                v1 = F[i1] * R[i1];                                           \
            }                                                                 \
            *(half2*)&smB[BUF][col * PH + (x - cc_)] = __floats2half2_rn(v0, v1); \
        }                                                                     \
    }                                                                         \
} while (0)

    G3STAGE(0, 0);
    __syncthreads();

    const int m0 = wm * 32;
    const int n0 = wn * 48;
    const int rowA = m0 + (lane & 7) + ((lane >> 3) & 1) * 8;
    const int kA   = (lane >> 4) * 8;
    const int rowB = n0 + (lane >> 4) * 8 + (lane & 7);
    const int kB   = ((lane >> 3) & 1) * 8;

    for (int s = 0; s < 8; s++) {
        int buf = s & 1;
        if (s + 1 < 8) G3STAGE(s + 1, buf ^ 1);

        const uint32_t aBase = smA0 + buf * (A_BUF_H * 2);
        const uint32_t bBase = smB0 + buf * (B_BUF_H * 2);
#pragma unroll
        for (int k0 = 0; k0 < 32; k0 += 16) {
            uint32_t af[2][4];
#pragma unroll
            for (int mt = 0; mt < 2; mt++)
                ldsm_x4(af[mt], aBase + (uint32_t)((rowA + mt * 16) * PH + k0 + kA) * 2);
            uint32_t bf[6][2];
#pragma unroll
            for (int ntp = 0; ntp < 3; ntp++) {
                uint32_t rr[4];
                ldsm_x4(rr, bBase + (uint32_t)((rowB + ntp * 16) * PH + k0 + kB) * 2);
                bf[2 * ntp][0] = rr[0]; bf[2 * ntp][1] = rr[1];
                bf[2 * ntp + 1][0] = rr[2]; bf[2 * ntp + 1][1] = rr[3];
            }
#pragma unroll
            for (int nt = 0; nt < 6; nt++) {
                mma_f16(acc[0][nt], af[0], bf[nt]);
                mma_f16(acc[1][nt], af[1], bf[nt]);
            }
        }
        __syncthreads();
    }

#pragma unroll
    for (int mt = 0; mt < 2; mt++) {
#pragma unroll
        for (int half = 0; half < 2; half++) {
            int o = m0 + mt * 16 + half * 8 + (lane >> 2);
            float bv = __ldg(bias + o);
#pragma unroll
            for (int nt = 0; nt < 6; nt++) {
                int col = col0 + n0 + nt * 8 + (lane & 3) * 2;
#pragma unroll
                for (int u = 0; u < 2; u++) {
                    size_t idx = base + (size_t)o * NPOS + col + u;
                    float cand = tanhf(acc[mt][nt][half * 2 + u] + bv);
                    float z = g_z[idx];
                    float f = feat[idx];
                    dst[idx] = fmaf(gam, fmaf(f, 1.f - z, cand * z), f);
                }
            }
        }
    }
#undef G3STAGE
}

// ---------------------------------------------------------------------------
extern "C" void kernel_launch(void* const* d_in, const int* in_sizes, int n_in,
                              void* d_out, int out_size)
{
    const float* feat_rgb = (const float*)d_in[0];
    const float* feat_dep = (const float*)d_in[1];
    const float* ppm_w_r  = (const float*)d_in[2];
    const float* ppm_s_r  = (const float*)d_in[3];
    const float* ppm_b_r  = (const float*)d_in[4];
    const float* ppm_w_d  = (const float*)d_in[5];
    const float* ppm_s_d  = (const float*)d_in[6];
    const float* ppm_b_d  = (const float*)d_in[7];
    const float* pa_w     = (const float*)d_in[8];
    const float* wgt_r    = (const float*)d_in[9];
    const float* gruw_r   = (const float*)d_in[10];
    const float* grub_r   = (const float*)d_in[11];
    const float* gam_r    = (const float*)d_in[12];
    const float* wgt_d    = (const float*)d_in[13];
    const float* gruw_d   = (const float*)d_in[14];
    const float* grub_d   = (const float*)d_in[15];
    const float* gam_d    = (const float*)d_in[16];
    float* out = (float*)d_out;

    cudaFuncSetAttribute(conv_mma_kernel,
                         cudaFuncAttributeMaxDynamicSharedMemorySize, CONV_SMEM);

    wt_prep_kernel<<<(2*4*9*128*512 + 255) / 256, 256>>>(ppm_w_r, ppm_w_d);
    gwh_prep_kernel<<<(2*3*128*256 + 255) / 256, 256>>>(gruw_r, gruw_d);
    in_prep_kernel<<<(4*64*NPOS + 255) / 256, 256>>>(feat_rgb, feat_dep);
    conv_mma_kernel<<<dim3(48, 8), 256, CONV_SMEM>>>(ppm_s_r, ppm_b_r,
                                                     ppm_s_d, ppm_b_d, out);
    pa_kernel<<<288, 256>>>(out, pa_w);
    for (int it = 0; it < 2; it++) {
        g1a_kernel<<<dim3(36, 2, 2), 256>>>(out, it, wgt_r, wgt_d);
        g1b_kernel<<<dim3(1152, 2, 2), 256>>>(out, it);
        g2_mma_kernel<<<dim3(24, 2, 16), 256>>>(out, it, grub_r, grub_d);
        g3_mma_kernel<<<dim3(24, 1, 16), 256>>>(out, it, grub_r, grub_d,
                                                gam_r, gam_d);
    }
}